// round 11
// baseline (speedup 1.0000x reference)
#include <cuda_runtime.h>

constexpr int Nn = 4096;   // z rows
constexpr int Mm = 1024;   // e rows
constexpr int Dd = 64;     // feature dim

constexpr int NQ = 1024;                     // z-quarter per build block
constexpr int BK = 1024;                     // buckets per quarter
constexpr float LOb  = -6.0f;
constexpr float HIb  =  6.0f;
constexpr float INVW = BK / (HIb - LOb);

__device__ __forceinline__ int bucket_of(float v) {
    int k = (int)((v - LOb) * INVW);
    return min(max(k, 0), BK - 1);
}

// Scratch (no allocations allowed -> device globals)
__device__ __align__(16) float g_zt[Dd * Nn];    // z transposed: [D][N]
__device__ __align__(16) float g_et[Dd * Mm];    // e transposed: [D][M]
__device__ float g_pb[4 * Dd * Mm];              // per-query best, 4 z-quarters

// ---------------------------------------------------------------------------
// k1: 80 blocks x 256 threads. Blocks 0..63: 64-row z tile -> mask + copy +
// transpose into g_zt. Blocks 64..79: 64-row e tile -> transpose into g_et.
// Each thread: 4 independent float4 loads (MLP=4), one barrier total.
__global__ void __launch_bounds__(256) k1_prep(const float* __restrict__ z,
                                               const float* __restrict__ e,
                                               const int* __restrict__ idx,
                                               float* __restrict__ out) {
    __shared__ float tile[64][65];
    const int bx = blockIdx.x, t = threadIdx.x;
    const bool is_z = (bx < 64);
    const float* src = is_z ? z : e;
    const int r0 = is_z ? bx * 64 : (bx - 64) * 64;   // starting row

    // 4 coalesced float4 loads (rows r0 .. r0+63, 16 float4 per 64-col row)
    float4 vf[4]; int row[4], c4[4];
    #pragma unroll
    for (int i = 0; i < 4; i++) {
        int f = i * 256 + t;             // 0..1023
        row[i] = f >> 4;                 // local row
        c4[i]  = f & 15;                 // float4 index within row
        vf[i] = reinterpret_cast<const float4*>(src)[(r0 + row[i]) * 16 + c4[i]];
    }

    if (is_z) {
        // mask + copy straight from registers (out+1 region 4B aligned -> scalar)
        #pragma unroll
        for (int i = 0; i < 4; i++) {
            int gr = r0 + row[i], col = c4[i] * 4;
            int kk = idx[gr];
            float vv[4] = {vf[i].x, vf[i].y, vf[i].z, vf[i].w};
            #pragma unroll
            for (int c = 0; c < 4; c++) {
                out[1 + gr * Dd + col + c]           = (col + c < kk) ? vv[c] : 0.0f;
                out[1 + Nn * Dd + gr * Dd + col + c] = vv[c];
            }
        }
        if (bx == 0 && t == 0) out[0] = 0.0f;
    }

    // stage tile and transpose out
    #pragma unroll
    for (int i = 0; i < 4; i++) {
        tile[row[i]][c4[i] * 4 + 0] = vf[i].x;
        tile[row[i]][c4[i] * 4 + 1] = vf[i].y;
        tile[row[i]][c4[i] * 4 + 2] = vf[i].z;
        tile[row[i]][c4[i] * 4 + 3] = vf[i].w;
    }
    __syncthreads();

    const int d = t >> 2, p = t & 3;     // 64 d's x 4 row-chunks of 16
    float buf[16];
    #pragma unroll
    for (int j = 0; j < 16; j++) buf[j] = tile[p * 16 + j][d];
    float* dst = is_z ? (g_zt + d * Nn + r0 + p * 16)
                      : (g_et + d * Mm + r0 + p * 16);
    #pragma unroll
    for (int j = 0; j < 4; j++)
        reinterpret_cast<float4*>(dst)[j] =
            make_float4(buf[4 * j], buf[4 * j + 1], buf[4 * j + 2], buf[4 * j + 3]);
}

// ---------------------------------------------------------------------------
// k2: grid 256 = 64 columns x 4 z-quarters, 2 blocks/SM (full occupancy).
// Block (d,h): bucket its 1024-value quarter (1 value/thread), then each
// thread answers query m=t: scan own bucket + nearest nonempty bucket each
// side (located via boundary elements). Plain disjoint store to g_pb.
__global__ void __launch_bounds__(1024, 2) k2_nn() {
    __shared__ float S[NQ];          // bucket-grouped quarter (4 KB)
    __shared__ int   cnt[BK];        // hist -> exclusive starts (4 KB)
    __shared__ int   wtot[32];

    const int bx = blockIdx.x;       // 0..255
    const int d  = bx & 63;
    const int h  = bx >> 6;          // which z-quarter
    const int t  = threadIdx.x;
    const int lane = t & 31, wid = t >> 5;

    // Prefetch (coalesced, L2-resident from k1).
    float x = g_et[d * Mm + t];
    float v = g_zt[d * Nn + h * NQ + t];

    cnt[t] = 0;
    __syncthreads();

    // ---- histogram + within-bucket rank (1 ATOMS/thread) ----
    int b = bucket_of(v);
    int r = atomicAdd(&cnt[b], 1);
    __syncthreads();

    // ---- block exclusive scan, 1 bucket per thread ----
    int c = cnt[t];
    int inc = c;
    #pragma unroll
    for (int o = 1; o < 32; o <<= 1) {
        int n = __shfl_up_sync(0xFFFFFFFFu, inc, o);
        if (lane >= o) inc += n;
    }
    if (lane == 31) wtot[wid] = inc;
    __syncthreads();
    if (wid == 0) {
        int ws = wtot[lane];
        int wi = ws;
        #pragma unroll
        for (int o = 1; o < 32; o <<= 1) {
            int n = __shfl_up_sync(0xFFFFFFFFu, wi, o);
            if (lane >= o) wi += n;
        }
        wtot[lane] = wi - ws;            // exclusive warp offsets
    }
    __syncthreads();
    cnt[t] = (inc - c) + wtot[wid];      // exclusive start of bucket t
    __syncthreads();

    // ---- scatter: plain store (start + rank unique) ----
    S[cnt[b] + r] = v;
    __syncthreads();

    // ---- query: own bucket + nearest nonempty bucket each side ----
    int k0 = bucket_of(x);
    int start = cnt[k0];
    int end   = (k0 < BK - 1) ? cnt[k0 + 1] : NQ;

    float best = 1e30f;
    for (int j = start; j < end; j++)
        best = fminf(best, fabsf(S[j] - x));

    if (start > 0) {                     // nearest nonempty bucket below
        int bb = bucket_of(S[start - 1]);
        int lo = cnt[bb];                // its segment is [lo, start)
        for (int j = lo; j < start; j++)
            best = fminf(best, fabsf(S[j] - x));
    }
    if (end < NQ) {                      // nearest nonempty bucket above
        int bb = bucket_of(S[end]);
        int hi = (bb < BK - 1) ? cnt[bb + 1] : NQ;
        for (int j = end; j < hi; j++)
            best = fminf(best, fabsf(S[j] - x));
    }

    g_pb[h * (Dd * Mm) + d * Mm + t] = best;   // disjoint plain store
}

// ---------------------------------------------------------------------------
// k3: combine 4 quarters + reduce -> out[0] += sum(min^2) / 65536.
__global__ void __launch_bounds__(1024) k3_reduce(float* __restrict__ out) {
    __shared__ float red[32];
    int i = blockIdx.x * 1024 + threadIdx.x;
    float a = g_pb[i];
    float b = g_pb[Dd * Mm + i];
    float c = g_pb[2 * Dd * Mm + i];
    float d = g_pb[3 * Dd * Mm + i];
    float m = fminf(fminf(a, b), fminf(c, d));
    float val = m * m * (1.0f / (float)(Mm * Dd));
    const int lane = threadIdx.x & 31, wid = threadIdx.x >> 5;
    #pragma unroll
    for (int o = 16; o > 0; o >>= 1)
        val += __shfl_xor_sync(0xFFFFFFFFu, val, o);
    if (lane == 0) red[wid] = val;
    __syncthreads();
    if (wid == 0) {
        float sv = red[lane];
        #pragma unroll
        for (int o = 16; o > 0; o >>= 1)
            sv += __shfl_xor_sync(0xFFFFFFFFu, sv, o);
        if (lane == 0) atomicAdd(out, sv);
    }
}

// ---------------------------------------------------------------------------
extern "C" void kernel_launch(void* const* d_in, const int* in_sizes, int n_in,
                              void* d_out, int out_size) {
    const float* z = (const float*)d_in[0];
    const float* e = (const float*)d_in[1];
    const int* idx = (const int*)d_in[2];
    float* out = (float*)d_out;

    k1_prep<<<80, 256>>>(z, e, idx, out);
    k2_nn<<<256, 1024>>>();
    k3_reduce<<<64, 1024>>>(out);
}